// round 6
// baseline (speedup 1.0000x reference)
#include <cuda_runtime.h>
#include <cuda_bf16.h>
#include <cstdint>

#define NN 100000
#define EE 1600000
#define DD 128
#define NEXP 8
#define SCAN_NBLK 98
#define EPSV 1e-5f

// ================= scratch (static device globals) =================
__device__ int   g_deg[NN];
__device__ int   g_off[NN];
__device__ int   g_cur[NN];
__device__ float g_inv_deg[NN];
__device__ int   g_srcs[EE];
__device__ int   g_bsum[SCAN_NBLK];
__device__ int   g_is64;
__device__ float g_agg0[NN * DD];
__device__ float g_stats_s[NEXP * DD];
__device__ float g_stats_q[NEXP * DD];
__device__ float g_scale[NEXP * DD];
__device__ float g_shift[NEXP * DD];
__device__ char  g_wt_hi[16][65536];     // per (e,l): 2 chunks x [128n][128k] bf16, swizzled
__device__ char  g_wt_lo[16][65536];
__device__ float g_h_all[(size_t)NN * NEXP * DD];     // INTERLEAVED [N][8][128] pre-BN h
__device__ float g_agg1_all[(size_t)NN * NEXP * DD];  // INTERLEAVED [N][8][128]
__device__ float g_out_tmp[(size_t)NEXP * NN * DD];   // [8][N][128] layer-1 outputs

// ================= mma helpers =================
__device__ __forceinline__ uint32_t smem_u32(const void* p) {
    uint32_t a;
    asm("{ .reg .u64 t; cvta.to.shared.u64 t, %1; cvt.u32.u64 %0, t; }" : "=r"(a) : "l"(p));
    return a;
}
__device__ __forceinline__ void ldsm4(uint32_t* r, uint32_t addr) {
    asm volatile("ldmatrix.sync.aligned.m8n8.x4.shared.b16 {%0,%1,%2,%3}, [%4];"
        : "=r"(r[0]), "=r"(r[1]), "=r"(r[2]), "=r"(r[3]) : "r"(addr));
}
__device__ __forceinline__ void mma16816(float* d, const uint32_t* a, const uint32_t* b) {
    asm volatile("mma.sync.aligned.m16n8k16.row.col.f32.bf16.bf16.f32 "
        "{%0,%1,%2,%3}, {%4,%5,%6,%7}, {%8,%9}, {%0,%1,%2,%3};"
        : "+f"(d[0]), "+f"(d[1]), "+f"(d[2]), "+f"(d[3])
        : "r"(a[0]), "r"(a[1]), "r"(a[2]), "r"(a[3]), "r"(b[0]), "r"(b[1]));
}
__device__ __forceinline__ int swz(int row, int kbyte) {
    return row * 256 + ((((kbyte >> 4) ^ (row & 7)) << 4) | (kbyte & 15));
}

// ================= CSR build =================
__global__ void k_detect(const int* __restrict__ ei32) {
    if (threadIdx.x == 0) {
        int hz = 1;
        for (int i = 0; i < 64; i++)
            if (ei32[2 * i + 1] != 0) { hz = 0; break; }
        g_is64 = hz;
    }
}
__global__ void k_zero_deg() {
    int i = blockIdx.x * blockDim.x + threadIdx.x;
    if (i < NN) g_deg[i] = 0;
}
__global__ void k_zero_stats8() {
    int i = blockIdx.x * blockDim.x + threadIdx.x;
    if (i < NEXP * DD) { g_stats_s[i] = 0.f; g_stats_q[i] = 0.f; }
}
__global__ void k_count(const int* __restrict__ ei32) {
    int i = blockIdx.x * blockDim.x + threadIdx.x;
    if (i < EE) {
        int d = g_is64 ? ei32[2 * (EE + i)] : ei32[EE + i];
        if ((unsigned)d < NN) atomicAdd(&g_deg[d], 1);
    }
}
__global__ void k_scan1() {
    __shared__ int s[1024];
    int t = threadIdx.x;
    int i = blockIdx.x * 1024 + t;
    int v = (i < NN) ? g_deg[i] : 0;
    s[t] = v;
    __syncthreads();
    for (int d = 1; d < 1024; d <<= 1) {
        int add = (t >= d) ? s[t - d] : 0;
        __syncthreads();
        s[t] += add;
        __syncthreads();
    }
    if (i < NN) g_off[i] = s[t] - v;
    if (t == 1023) g_bsum[blockIdx.x] = s[1023];
}
__global__ void k_scan2() {
    if (threadIdx.x == 0) {
        int run = 0;
        for (int i = 0; i < SCAN_NBLK; i++) { int v = g_bsum[i]; g_bsum[i] = run; run += v; }
    }
}
__global__ void k_scan3() {
    int i = blockIdx.x * blockDim.x + threadIdx.x;
    if (i >= NN) return;
    int off = g_off[i] + g_bsum[i >> 10];
    g_off[i] = off;
    g_cur[i] = off;
    int dg = g_deg[i];
    g_inv_deg[i] = 1.0f / (float)(dg > 0 ? dg : 1);
}
__global__ void k_fill(const int* __restrict__ ei32) {
    int i = blockIdx.x * blockDim.x + threadIdx.x;
    if (i < EE) {
        int is64 = g_is64;
        int d = is64 ? ei32[2 * (EE + i)] : ei32[EE + i];
        int s = is64 ? ei32[2 * i]        : ei32[i];
        if ((unsigned)d < NN && (unsigned)s < NN) {
            int pos = atomicAdd(&g_cur[d], 1);
            g_srcs[pos] = s;
        }
    }
}

// ================= layer-0 aggregation (x, plain [N][128]) =================
__global__ void k_agg0(const float* __restrict__ feat, float* __restrict__ out) {
    int gw = (blockIdx.x * blockDim.x + threadIdx.x) >> 5;
    int lane = threadIdx.x & 31;
    if (gw >= NN) return;
    int start = g_off[gw];
    int cnt   = g_cur[gw] - start;
    const float4* f4 = (const float4*)feat;
    float4 acc = make_float4(0.f, 0.f, 0.f, 0.f);
    int j = 0;
#define GB(U) \
    { \
        int s[U]; \
        _Pragma("unroll") for (int u = 0; u < U; u++) s[u] = g_srcs[start + j + u]; \
        float4 v[U]; \
        _Pragma("unroll") for (int u = 0; u < U; u++) v[u] = f4[s[u] * 32 + lane]; \
        _Pragma("unroll") for (int u = 0; u < U; u++) { \
            acc.x += v[u].x; acc.y += v[u].y; acc.z += v[u].z; acc.w += v[u].w; \
        } \
        j += U; \
    }
    for (; j + 8 <= cnt;) GB(8)
    if (j + 4 <= cnt) GB(4)
    if (j + 2 <= cnt) GB(2)
    if (j + 1 <= cnt) GB(1)
#undef GB
    float sc = g_inv_deg[gw];
    ((float4*)out)[gw * 32 + lane] =
        make_float4(acc.x * sc, acc.y * sc, acc.z * sc, acc.w * sc);
}

// ================= batched layer-1 aggregation: all 8 experts, interleaved h =================
// 2 warps per node: warp half eh owns experts eh*4..eh*4+3. BN+ReLU fused on gather.
__global__ void k_agg_all(const float* __restrict__ hI, float* __restrict__ aggI) {
    int gw = (blockIdx.x * blockDim.x + threadIdx.x) >> 5;
    int lane = threadIdx.x & 31;
    int node = gw >> 1;
    int eh   = gw & 1;
    if (node >= NN) return;
    int e0 = eh * 4;
    int start = g_off[node];
    int cnt   = g_cur[node] - start;
    const float4* f4 = (const float4*)hI;   // node s record: f4[s*256 + e*32 + lane]

    float4 sc[4], sh[4], acc[4];
#pragma unroll
    for (int j = 0; j < 4; j++) {
        sc[j] = ((const float4*)g_scale)[(e0 + j) * 32 + lane];
        sh[j] = ((const float4*)g_shift)[(e0 + j) * 32 + lane];
        acc[j] = make_float4(0.f, 0.f, 0.f, 0.f);
    }

    int j = 0;
#define GB(U) \
    { \
        int s[U]; \
        _Pragma("unroll") for (int u = 0; u < U; u++) s[u] = g_srcs[start + j + u]; \
        float4 v[U][4]; \
        _Pragma("unroll") for (int u = 0; u < U; u++) { \
            size_t base = (size_t)s[u] * 256 + (size_t)e0 * 32 + lane; \
            _Pragma("unroll") for (int q = 0; q < 4; q++) v[u][q] = f4[base + q * 32]; \
        } \
        _Pragma("unroll") for (int u = 0; u < U; u++) \
            _Pragma("unroll") for (int q = 0; q < 4; q++) { \
                float4 t = v[u][q]; \
                t.x = fmaxf(fmaf(t.x, sc[q].x, sh[q].x), 0.f); \
                t.y = fmaxf(fmaf(t.y, sc[q].y, sh[q].y), 0.f); \
                t.z = fmaxf(fmaf(t.z, sc[q].z, sh[q].z), 0.f); \
                t.w = fmaxf(fmaf(t.w, sc[q].w, sh[q].w), 0.f); \
                acc[q].x += t.x; acc[q].y += t.y; acc[q].z += t.z; acc[q].w += t.w; \
            } \
        j += U; \
    }
    for (; j + 2 <= cnt;) GB(2)
    if (j < cnt) GB(1)
#undef GB

    float idg = g_inv_deg[node];
    float4* o = (float4*)aggI;
#pragma unroll
    for (int q = 0; q < 4; q++)
        o[(size_t)node * 256 + (size_t)(e0 + q) * 32 + lane] =
            make_float4(acc[q].x * idg, acc[q].y * idg, acc[q].z * idg, acc[q].w * idg);
}

// ================= weight prep =================
__global__ void k_prep_w(const float* __restrict__ Wself, const float* __restrict__ Wnbr) {
    int inst = blockIdx.x;
    const float* ws = Wself + (size_t)inst * DD * DD;
    const float* wn = Wnbr  + (size_t)inst * DD * DD;
    char* dh = g_wt_hi[inst];
    char* dl = g_wt_lo[inst];
    for (int idx = threadIdx.x; idx < 256 * 128; idx += blockDim.x) {
        int n = idx & 127;
        int k = idx >> 7;
        float w = (k < 128) ? ws[k * 128 + n] : wn[(k - 128) * 128 + n];
        __nv_bfloat16 hi = __float2bfloat16(w);
        __nv_bfloat16 lo = __float2bfloat16(w - __bfloat162float(hi));
        int chunk = k >> 7;
        int kk = k & 127;
        int off = chunk * 32768 + swz(n, kk * 2);
        *(__nv_bfloat16*)(dh + off) = hi;
        *(__nv_bfloat16*)(dl + off) = lo;
    }
}

// ================= A-tile conversion =================
// plain [N][128] source
__device__ __forceinline__ void convert_A_plain(char* sm, int base, const float* __restrict__ src,
                                                int n0, int tid) {
    for (int idx = tid; idx < 4096; idx += 256) {
        int r  = idx >> 5;
        int kg = idx & 31;
        int n  = n0 + r;
        float4 v = make_float4(0.f, 0.f, 0.f, 0.f);
        if (n < NN) v = ((const float4*)src)[n * 32 + kg];
        int off = swz(r, kg * 8);
        __nv_bfloat16 hx = __float2bfloat16(v.x);
        __nv_bfloat16 hy = __float2bfloat16(v.y);
        __nv_bfloat16 hz = __float2bfloat16(v.z);
        __nv_bfloat16 hw = __float2bfloat16(v.w);
        __nv_bfloat16 lx = __float2bfloat16(v.x - __bfloat162float(hx));
        __nv_bfloat16 ly = __float2bfloat16(v.y - __bfloat162float(hy));
        __nv_bfloat16 lz = __float2bfloat16(v.z - __bfloat162float(hz));
        __nv_bfloat16 lw = __float2bfloat16(v.w - __bfloat162float(hw));
        uint2 ph, pl;
        ph.x = ((uint32_t)__bfloat16_as_ushort(hy) << 16) | __bfloat16_as_ushort(hx);
        ph.y = ((uint32_t)__bfloat16_as_ushort(hw) << 16) | __bfloat16_as_ushort(hz);
        pl.x = ((uint32_t)__bfloat16_as_ushort(ly) << 16) | __bfloat16_as_ushort(lx);
        pl.y = ((uint32_t)__bfloat16_as_ushort(lw) << 16) | __bfloat16_as_ushort(lz);
        *(uint2*)(sm + base + off) = ph;
        *(uint2*)(sm + base + 32768 + off) = pl;
    }
}
// interleaved [N][8][128] source, optional BN+ReLU
template <bool BN>
__device__ __forceinline__ void convert_A_I(char* sm, int base, const float* __restrict__ srcI,
                                            int e, const float* __restrict__ scale,
                                            const float* __restrict__ shift,
                                            int n0, int tid) {
    for (int idx = tid; idx < 4096; idx += 256) {
        int r  = idx >> 5;
        int kg = idx & 31;
        int n  = n0 + r;
        float4 v = make_float4(0.f, 0.f, 0.f, 0.f);
        if (n < NN) v = ((const float4*)srcI)[(size_t)n * 256 + (size_t)e * 32 + kg];
        if (BN) {
            float4 sc = ((const float4*)scale)[kg];
            float4 sh = ((const float4*)shift)[kg];
            v.x = fmaxf(fmaf(v.x, sc.x, sh.x), 0.f);
            v.y = fmaxf(fmaf(v.y, sc.y, sh.y), 0.f);
            v.z = fmaxf(fmaf(v.z, sc.z, sh.z), 0.f);
            v.w = fmaxf(fmaf(v.w, sc.w, sh.w), 0.f);
        }
        int off = swz(r, kg * 8);
        __nv_bfloat16 hx = __float2bfloat16(v.x);
        __nv_bfloat16 hy = __float2bfloat16(v.y);
        __nv_bfloat16 hz = __float2bfloat16(v.z);
        __nv_bfloat16 hw = __float2bfloat16(v.w);
        __nv_bfloat16 lx = __float2bfloat16(v.x - __bfloat162float(hx));
        __nv_bfloat16 ly = __float2bfloat16(v.y - __bfloat162float(hy));
        __nv_bfloat16 lz = __float2bfloat16(v.z - __bfloat162float(hz));
        __nv_bfloat16 lw = __float2bfloat16(v.w - __bfloat162float(hw));
        uint2 ph, pl;
        ph.x = ((uint32_t)__bfloat16_as_ushort(hy) << 16) | __bfloat16_as_ushort(hx);
        ph.y = ((uint32_t)__bfloat16_as_ushort(hw) << 16) | __bfloat16_as_ushort(hz);
        pl.x = ((uint32_t)__bfloat16_as_ushort(ly) << 16) | __bfloat16_as_ushort(lx);
        pl.y = ((uint32_t)__bfloat16_as_ushort(lw) << 16) | __bfloat16_as_ushort(lz);
        *(uint2*)(sm + base + off) = ph;
        *(uint2*)(sm + base + 32768 + off) = pl;
    }
}

// ================= MMA core (shared by both GEMM kernels) =================
struct MmaCtx {
    int lrowA, lkgA, lnB, lkgB, wr, wc;
};
__device__ __forceinline__ void mma_chunk(uint32_t smb, int abase, int bbase,
                                          const MmaCtx& c, float acc[2][8][4]) {
#pragma unroll
    for (int ks = 0; ks < 8; ks++) {
        uint32_t ah[2][4], al[2][4], bh[4][4], bl[4][4];
#pragma unroll
        for (int at = 0; at < 2; at++) {
            int row = c.wr * 32 + at * 16 + c.lrowA;
            int kb  = (ks * 2 + c.lkgA) * 16;
            uint32_t off = (uint32_t)swz(row, kb);
            ldsm4(ah[at], smb + abase + off);
            ldsm4(al[at], smb + abase + 32768 + off);
        }
#pragma unroll
        for (int bp = 0; bp < 4; bp++) {
            int nrow = c.wc * 64 + bp * 16 + c.lnB;
            int kb   = (ks * 2 + c.lkgB) * 16;
            uint32_t off = (uint32_t)swz(nrow, kb);
            ldsm4(bh[bp], smb + bbase + off);
            ldsm4(bl[bp], smb + bbase + 32768 + off);
        }
#pragma unroll
        for (int at = 0; at < 2; at++)
#pragma unroll
            for (int bp = 0; bp < 4; bp++)
#pragma unroll
                for (int hf = 0; hf < 2; hf++) {
                    float* d = acc[at][bp * 2 + hf];
                    mma16816(d, ah[at], &bh[bp][hf * 2]);
                    mma16816(d, ah[at], &bl[bp][hf * 2]);
                    mma16816(d, al[at], &bh[bp][hf * 2]);
                }
    }
}

// ================= batched layer-0 GEMM: all experts, A converted once =================
// smem: A both chunks [c0hi,c0lo,c1hi,c1lo] 0..131071 ; B [hi,lo] 131072..196607
#define G0_B 131072
#define G0_TOTAL 196608

__global__ void __launch_bounds__(256, 1)
k_gemm0_all(const float* __restrict__ x, const float* __restrict__ agg0,
            const char* __restrict__ wth_all, const char* __restrict__ wtl_all,
            const float* __restrict__ bprm, float* __restrict__ hI)
{
    extern __shared__ char sm[];
    uint32_t smb = smem_u32(sm);
    int tid = threadIdx.x, wid = tid >> 5, lane = tid & 31;
    int n0 = blockIdx.x * 128;
    MmaCtx c;
    c.wr = wid & 3; c.wc = wid >> 2;
    c.lrowA = lane & 15; c.lkgA = lane >> 4;
    c.lnB = (lane & 7) + ((lane >> 4) << 3); c.lkgB = (lane >> 3) & 1;
    int trow = lane >> 2, tc2 = lane & 3;

    convert_A_plain(sm, 0,     x,    n0, tid);
    convert_A_plain(sm, 65536, agg0, n0, tid);

    for (int e = 0; e < NEXP; e++) {
        float acc[2][8][4];
#pragma unroll
        for (int a = 0; a < 2; a++)
#pragma unroll
            for (int b = 0; b < 8; b++)
#pragma unroll
                for (int q = 0; q < 4; q++) acc[a][b][q] = 0.f;

        const char* wh = wth_all + (size_t)(e * 2) * 65536;
        const char* wl = wtl_all + (size_t)(e * 2) * 65536;

#pragma unroll
        for (int chunk = 0; chunk < 2; chunk++) {
            __syncthreads();
            {
                const uint4* s0 = (const uint4*)(wh + chunk * 32768);
                const uint4* s1 = (const uint4*)(wl + chunk * 32768);
                uint4* d0 = (uint4*)(sm + G0_B);
                uint4* d1 = (uint4*)(sm + G0_B + 32768);
                for (int i = tid; i < 2048; i += 256) { d0[i] = s0[i]; d1[i] = s1[i]; }
            }
            __syncthreads();
            mma_chunk(smb, chunk * 65536, G0_B, c, acc);
        }

        // epilogue: bias, store INTERLEAVED h, fused column stats
        const float* be = bprm + (size_t)(e * 2) * DD;
        float2* o = (float2*)hI;
#pragma unroll
        for (int bt = 0; bt < 8; bt++) {
            int col = c.wc * 64 + bt * 8 + tc2 * 2;
            float bx = be[col], by = be[col + 1];
            float sx = 0.f, sy = 0.f, qx = 0.f, qy = 0.f;
#pragma unroll
            for (int at = 0; at < 2; at++) {
                int r0 = n0 + c.wr * 32 + at * 16 + trow;
                float v0x = acc[at][bt][0] + bx, v0y = acc[at][bt][1] + by;
                float v1x = acc[at][bt][2] + bx, v1y = acc[at][bt][3] + by;
                if (r0 < NN) {
                    o[((size_t)r0 * 8 + e) * 64 + (col >> 1)] = make_float2(v0x, v0y);
                    sx += v0x; sy += v0y; qx += v0x * v0x; qy += v0y * v0y;
                }
                if (r0 + 8 < NN) {
                    o[((size_t)(r0 + 8) * 8 + e) * 64 + (col >> 1)] = make_float2(v1x, v1y);
                    sx += v1x; sy += v1y; qx += v1x * v1x; qy += v1y * v1y;
                }
            }
#pragma unroll
            for (int off = 4; off < 32; off <<= 1) {
                sx += __shfl_xor_sync(0xFFFFFFFF, sx, off);
                sy += __shfl_xor_sync(0xFFFFFFFF, sy, off);
                qx += __shfl_xor_sync(0xFFFFFFFF, qx, off);
                qy += __shfl_xor_sync(0xFFFFFFFF, qy, off);
            }
            if (lane < 4) {
                atomicAdd(&g_stats_s[e * DD + col], sx);
                atomicAdd(&g_stats_s[e * DD + col + 1], sy);
                atomicAdd(&g_stats_q[e * DD + col], qx);
                atomicAdd(&g_stats_q[e * DD + col + 1], qy);
            }
        }
    }
}

// ================= finalize BN =================
__global__ void k_finalize(const float* __restrict__ gamma, const float* __restrict__ beta) {
    int i = threadIdx.x + blockIdx.x * blockDim.x;
    if (i >= NEXP * DD) return;
    const float invn = 1.0f / (float)NN;
    float m = g_stats_s[i] * invn;
    float var = g_stats_q[i] * invn - m * m;
    float r = rsqrtf(var + EPSV);
    float sc = gamma[i] * r;
    g_scale[i] = sc;
    g_shift[i] = beta[i] - m * sc;
}

// ================= batched layer-1 GEMM: all experts in one launch =================
// smem: A one chunk [hi,lo] 0..65535 ; B [hi,lo] 65536..131071
#define G1_B 65536
#define G1_TOTAL 131072

__global__ void __launch_bounds__(256, 1)
k_gemm1_all(const float* __restrict__ hI, const float* __restrict__ aggI,
            const char* __restrict__ wth_all, const char* __restrict__ wtl_all,
            const float* __restrict__ bprm,
            const float* __restrict__ scale, const float* __restrict__ shift,
            float* __restrict__ otmp)
{
    extern __shared__ char sm[];
    uint32_t smb = smem_u32(sm);
    int tid = threadIdx.x, wid = tid >> 5, lane = tid & 31;
    int n0 = blockIdx.x * 128;
    MmaCtx c;
    c.wr = wid & 3; c.wc = wid >> 2;
    c.lrowA = lane & 15; c.lkgA = lane >> 4;
    c.lnB = (lane & 7) + ((lane >> 4) << 3); c.lkgB = (lane >> 3) & 1;
    int trow = lane >> 2, tc2 = lane & 3;

    for (int e = 0; e < NEXP; e++) {
        float acc[2][8][4];
#pragma unroll
        for (int a = 0; a < 2; a++)
#pragma unroll
            for (int b = 0; b < 8; b++)
#pragma unroll
                for (int q = 0; q < 4; q++) acc[a][b][q] = 0.f;

        const char* wh = wth_all + (size_t)(e * 2 + 1) * 65536;
        const char* wl = wtl_all + (size_t)(e * 2 + 1) * 65536;

#pragma unroll
        for (int chunk = 0; chunk < 2; chunk++) {
            __syncthreads();
            {
                const uint4* s0 = (const uint4*)(wh + chunk * 32768);
                const uint4* s1 = (const uint4*)(wl + chunk * 32768);
                uint4* d0 = (uint4*)(sm + G1_B);
                uint4* d1 = (uint4*)(sm + G1_B + 32768);
                for (int i = tid; i < 2048; i += 256) { d0[i] = s0[i]; d1[i] = s1[i]; }
            }
            if (chunk == 0)
                convert_A_I<true>(sm, 0, hI, e, scale + e * DD, shift + e * DD, n0, tid);
            else
                convert_A_I<false>(sm, 0, aggI, e, nullptr, nullptr, n0, tid);
            __syncthreads();
            mma_chunk(smb, 0, G1_B, c, acc);
        }

        const float* be = bprm + (size_t)(e * 2 + 1) * DD;
        float2* o = (float2*)(otmp + (size_t)e * NN * DD);
#pragma unroll
        for (int at = 0; at < 2; at++)
#pragma unroll
            for (int bt = 0; bt < 8; bt++) {
                int col = c.wc * 64 + bt * 8 + tc2 * 2;
                float bx = be[col], by = be[col + 1];
                int r0 = n0 + c.wr * 32 + at * 16 + trow;
                if (r0 < NN)
                    o[r0 * 64 + (col >> 1)] =
                        make_float2(acc[at][bt][0] + bx, acc[at][bt][1] + by);
                if (r0 + 8 < NN)
                    o[(r0 + 8) * 64 + (col >> 1)] =
                        make_float2(acc[at][bt][2] + bx, acc[at][bt][3] + by);
            }
    }
}

// ================= final interleave [8][N][128] -> [N][128][8] =================
__global__ void k_interleave(float* __restrict__ out) {
    int idx = blockIdx.x * blockDim.x + threadIdx.x;
    if (idx >= NN * DD) return;
    float v[8];
#pragma unroll
    for (int e = 0; e < 8; e++) v[e] = g_out_tmp[(size_t)e * (NN * DD) + idx];
    float4* o = (float4*)out + (size_t)idx * 2;
    o[0] = make_float4(v[0], v[1], v[2], v[3]);
    o[1] = make_float4(v[4], v[5], v[6], v[7]);
}

// ================= launch =================
extern "C" void kernel_launch(void* const* d_in, const int* in_sizes, int n_in,
                              void* d_out, int out_size)
{
    const float* x      = (const float*)d_in[0];
    const int*   ei32   = (const int*)d_in[1];
    const float* W_self = (const float*)d_in[2];
    const float* W_nbr  = (const float*)d_in[3];
    const float* bprm   = (const float*)d_in[4];
    const float* gamma  = (const float*)d_in[5];
    const float* beta   = (const float*)d_in[6];
    float*       out    = (float*)d_out;

    cudaFuncSetAttribute(k_gemm0_all, cudaFuncAttributeMaxDynamicSharedMemorySize, G0_TOTAL);
    cudaFuncSetAttribute(k_gemm1_all, cudaFuncAttributeMaxDynamicSharedMemorySize, G1_TOTAL);

    float *agg0, *agg1I, *hI, *otmp, *scl, *shf;
    char *wth, *wtl;
    cudaGetSymbolAddress((void**)&agg0,  g_agg0);
    cudaGetSymbolAddress((void**)&agg1I, g_agg1_all);
    cudaGetSymbolAddress((void**)&hI,    g_h_all);
    cudaGetSymbolAddress((void**)&otmp,  g_out_tmp);
    cudaGetSymbolAddress((void**)&scl,   g_scale);
    cudaGetSymbolAddress((void**)&shf,   g_shift);
    cudaGetSymbolAddress((void**)&wth,   g_wt_hi);
    cudaGetSymbolAddress((void**)&wtl,   g_wt_lo);

    // CSR build
    k_detect<<<1, 32>>>(ei32);
    k_zero_deg<<<(NN + 255) / 256, 256>>>();
    k_zero_stats8<<<1, 1024>>>();
    k_count<<<EE / 256, 256>>>(ei32);
    k_scan1<<<SCAN_NBLK, 1024>>>();
    k_scan2<<<1, 32>>>();
    k_scan3<<<(NN + 255) / 256, 256>>>();
    k_fill<<<EE / 256, 256>>>(ei32);

    // weight prep + layer-0 aggregation
    k_prep_w<<<16, 256>>>(W_self, W_nbr);
    k_agg0<<<NN / 8, 256>>>(x, agg0);

    const int NB = (NN + 127) / 128;   // 782

    // layer 0: all experts, one launch (+ fused stats), interleaved h out
    k_gemm0_all<<<NB, 256, G0_TOTAL>>>(x, agg0, wth, wtl, bprm, hI);
    k_finalize<<<1, 1024>>>(gamma, beta);

    // layer 1: batched aggregation (1 launch) + batched GEMM (1 launch)
    k_agg_all<<<(NN * 2 + 7) / 8, 256>>>(hI, agg1I);
    k_gemm1_all<<<NB, 256, G1_TOTAL>>>(hI, agg1I, wth, wtl, bprm, scl, shf, otmp);

    k_interleave<<<(NN * DD) / 256, 256>>>(out);
}

// round 7
// speedup vs baseline: 1.2668x; 1.2668x over previous
#include <cuda_runtime.h>
#include <cuda_bf16.h>
#include <cstdint>

#define NN 100000
#define EE 1600000
#define DD 128
#define NEXP 8
#define EPSV 1e-5f
#define NBLK 296
#define GT (NBLK * 256)

// ================= scratch (static device globals) =================
__device__ int   g_deg[NN];
__device__ int   g_off[NN];
__device__ int   g_cur[NN];
__device__ float g_inv_deg[NN];
__device__ int   g_srcs[EE];
__device__ int   g_bsum2[NBLK];
__device__ int   g_barrier[8];
__device__ int   g_is64;
__device__ float g_agg0[NN * DD];
__device__ float g_stats_s[NEXP * DD];
__device__ float g_stats_q[NEXP * DD];
__device__ float g_scale[NEXP * DD];
__device__ float g_shift[NEXP * DD];
__device__ char  g_wt_hi[16][65536];     // per (e,l): 2 chunks x [128n][128k] bf16, swizzled
__device__ char  g_wt_lo[16][65536];
__device__ float g_h_all[(size_t)NEXP * NN * DD];     // [8][N][128] pre-BN layer-0 h
__device__ float g_agg1_all[(size_t)NEXP * NN * DD];  // [8][N][128]
__device__ float g_out_tmp[(size_t)NEXP * NN * DD];   // [8][N][128] layer-1 outputs

// ================= mma helpers =================
__device__ __forceinline__ uint32_t smem_u32(const void* p) {
    uint32_t a;
    asm("{ .reg .u64 t; cvta.to.shared.u64 t, %1; cvt.u32.u64 %0, t; }" : "=r"(a) : "l"(p));
    return a;
}
__device__ __forceinline__ void ldsm4(uint32_t* r, uint32_t addr) {
    asm volatile("ldmatrix.sync.aligned.m8n8.x4.shared.b16 {%0,%1,%2,%3}, [%4];"
        : "=r"(r[0]), "=r"(r[1]), "=r"(r[2]), "=r"(r[3]) : "r"(addr));
}
__device__ __forceinline__ void mma16816(float* d, const uint32_t* a, const uint32_t* b) {
    asm volatile("mma.sync.aligned.m16n8k16.row.col.f32.bf16.bf16.f32 "
        "{%0,%1,%2,%3}, {%4,%5,%6,%7}, {%8,%9}, {%0,%1,%2,%3};"
        : "+f"(d[0]), "+f"(d[1]), "+f"(d[2]), "+f"(d[3])
        : "r"(a[0]), "r"(a[1]), "r"(a[2]), "r"(a[3]), "r"(b[0]), "r"(b[1]));
}
__device__ __forceinline__ int swz(int row, int kbyte) {
    return row * 256 + ((((kbyte >> 4) ^ (row & 7)) << 4) | (kbyte & 15));
}

// ================= software grid barrier (counters reset by k_init each launch) ======
__device__ __forceinline__ void grid_bar(int slot) {
    __syncthreads();
    if (threadIdx.x == 0) {
        __threadfence();
        int arrived = atomicAdd(&g_barrier[slot], 1) + 1;
        if (arrived < NBLK) {
            while (((volatile int*)g_barrier)[slot] < NBLK) { }
        }
        __threadfence();
    }
    __syncthreads();
}

// ================= init: reset barriers, zero stats, dtype detect =================
__global__ void k_init(const int* __restrict__ ei32) {
    int t = threadIdx.x;
    if (t < 8) g_barrier[t] = 0;
    for (int i = t; i < NEXP * DD; i += 1024) { g_stats_s[i] = 0.f; g_stats_q[i] = 0.f; }
    if (t == 0) {
        int hz = 1;
        for (int i = 0; i < 64; i++)
            if (ei32[2 * i + 1] != 0) { hz = 0; break; }
        g_is64 = hz;
    }
}

// ================= fused CSR build + layer-0 aggregation (persistent, grid barriers) ==
__global__ void __launch_bounds__(256)
k_csr_agg0(const int* __restrict__ ei32, const float* __restrict__ x,
           float* __restrict__ agg0)
{
    int tid = threadIdx.x, b = blockIdx.x;
    int gt = b * 256 + tid;
    __shared__ int s[256];
    __shared__ int bs[NBLK];

    // phase 0: zero degrees
    for (int i = gt; i < NN; i += GT) g_deg[i] = 0;
    grid_bar(0);

    // phase 1: count
    int is64 = g_is64;
    for (int i = gt; i < EE; i += GT) {
        int d = is64 ? ei32[2 * (EE + i)] : ei32[EE + i];
        if ((unsigned)d < NN) atomicAdd(&g_deg[d], 1);
    }
    grid_bar(1);

    // phase 2: per-thread (2 elems) sums + block inclusive scan
    int base0 = gt * 2;
    int d0 = (base0     < NN) ? g_deg[base0]     : 0;
    int d1 = (base0 + 1 < NN) ? g_deg[base0 + 1] : 0;
    int tsum = d0 + d1;
    s[tid] = tsum;
    __syncthreads();
    for (int o = 1; o < 256; o <<= 1) {
        int a = (tid >= o) ? s[tid - o] : 0;
        __syncthreads();
        s[tid] += a;
        __syncthreads();
    }
    if (tid == 255) g_bsum2[b] = s[255];
    grid_bar(2);

    // phase 3: block 0 scans block sums
    if (b == 0) {
        for (int i = tid; i < NBLK; i += 256) bs[i] = g_bsum2[i];
        __syncthreads();
        if (tid == 0) {
            int run = 0;
            for (int i = 0; i < NBLK; i++) { int v = bs[i]; bs[i] = run; run += v; }
        }
        __syncthreads();
        for (int i = tid; i < NBLK; i += 256) g_bsum2[i] = bs[i];
    }
    grid_bar(3);

    // phase 4: offsets / cursors / inv_deg
    {
        int tbase = g_bsum2[b] + (s[tid] - tsum);
        if (base0 < NN) {
            g_off[base0] = tbase;
            g_cur[base0] = tbase;
            g_inv_deg[base0] = 1.0f / (float)(d0 > 0 ? d0 : 1);
        }
        if (base0 + 1 < NN) {
            int o1 = tbase + d0;
            g_off[base0 + 1] = o1;
            g_cur[base0 + 1] = o1;
            g_inv_deg[base0 + 1] = 1.0f / (float)(d1 > 0 ? d1 : 1);
        }
    }
    grid_bar(4);

    // phase 5: fill
    for (int i = gt; i < EE; i += GT) {
        int d  = is64 ? ei32[2 * (EE + i)] : ei32[EE + i];
        int sv = is64 ? ei32[2 * i]        : ei32[i];
        if ((unsigned)d < NN && (unsigned)sv < NN) {
            int pos = atomicAdd(&g_cur[d], 1);
            g_srcs[pos] = sv;
        }
    }
    grid_bar(5);

    // phase 6: layer-0 aggregation (warp per node, unrolled gather)
    {
        int gw = gt >> 5, lane = tid & 31;
        const int NW = NBLK * 8;
        const float4* f4 = (const float4*)x;
        for (int node = gw; node < NN; node += NW) {
            int start = g_off[node];
            int cnt   = g_cur[node] - start;
            float4 acc = make_float4(0.f, 0.f, 0.f, 0.f);
            int j = 0;
#define GB(U) \
            { \
                int si[U]; \
                _Pragma("unroll") for (int u = 0; u < U; u++) si[u] = g_srcs[start + j + u]; \
                float4 v[U]; \
                _Pragma("unroll") for (int u = 0; u < U; u++) v[u] = f4[si[u] * 32 + lane]; \
                _Pragma("unroll") for (int u = 0; u < U; u++) { \
                    acc.x += v[u].x; acc.y += v[u].y; acc.z += v[u].z; acc.w += v[u].w; \
                } \
                j += U; \
            }
            for (; j + 8 <= cnt;) GB(8)
            if (j + 4 <= cnt) GB(4)
            if (j + 2 <= cnt) GB(2)
            if (j + 1 <= cnt) GB(1)
#undef GB
            float scv = g_inv_deg[node];
            ((float4*)agg0)[node * 32 + lane] =
                make_float4(acc.x * scv, acc.y * scv, acc.z * scv, acc.w * scv);
        }
    }
}

// ================= per-expert layer-1 aggregation (BN+ReLU fused on gather) ==========
__global__ void k_agg(const float* __restrict__ feat, float* __restrict__ out,
                      const float* __restrict__ scale, const float* __restrict__ shift)
{
    int gw = (blockIdx.x * blockDim.x + threadIdx.x) >> 5;
    int lane = threadIdx.x & 31;
    if (gw >= NN) return;
    int start = g_off[gw];
    int cnt   = g_cur[gw] - start;
    const float4* f4 = (const float4*)feat;
    float4 sc4 = ((const float4*)scale)[lane];
    float4 sh4 = ((const float4*)shift)[lane];
    float4 acc = make_float4(0.f, 0.f, 0.f, 0.f);
    int j = 0;
#define GB(U) \
    { \
        int si[U]; \
        _Pragma("unroll") for (int u = 0; u < U; u++) si[u] = g_srcs[start + j + u]; \
        float4 v[U]; \
        _Pragma("unroll") for (int u = 0; u < U; u++) v[u] = f4[si[u] * 32 + lane]; \
        _Pragma("unroll") for (int u = 0; u < U; u++) { \
            float4 t = v[u]; \
            t.x = fmaxf(fmaf(t.x, sc4.x, sh4.x), 0.f); \
            t.y = fmaxf(fmaf(t.y, sc4.y, sh4.y), 0.f); \
            t.z = fmaxf(fmaf(t.z, sc4.z, sh4.z), 0.f); \
            t.w = fmaxf(fmaf(t.w, sc4.w, sh4.w), 0.f); \
            acc.x += t.x; acc.y += t.y; acc.z += t.z; acc.w += t.w; \
        } \
        j += U; \
    }
    for (; j + 8 <= cnt;) GB(8)
    if (j + 4 <= cnt) GB(4)
    if (j + 2 <= cnt) GB(2)
    if (j + 1 <= cnt) GB(1)
#undef GB
    float scv = g_inv_deg[gw];
    ((float4*)out)[gw * 32 + lane] =
        make_float4(acc.x * scv, acc.y * scv, acc.z * scv, acc.w * scv);
}

// ================= weight prep: fuse [Wself;Wnbr], transpose, bf16-split, swizzle =====
__global__ void k_prep_w(const float* __restrict__ Wself, const float* __restrict__ Wnbr) {
    int inst = blockIdx.x;
    const float* ws = Wself + (size_t)inst * DD * DD;
    const float* wn = Wnbr  + (size_t)inst * DD * DD;
    char* dh = g_wt_hi[inst];
    char* dl = g_wt_lo[inst];
    for (int idx = threadIdx.x; idx < 256 * 128; idx += blockDim.x) {
        int n = idx & 127;
        int k = idx >> 7;
        float w = (k < 128) ? ws[k * 128 + n] : wn[(k - 128) * 128 + n];
        __nv_bfloat16 hi = __float2bfloat16(w);
        __nv_bfloat16 lo = __float2bfloat16(w - __bfloat162float(hi));
        int chunk = k >> 7;
        int kk = k & 127;
        int off = chunk * 32768 + swz(n, kk * 2);
        *(__nv_bfloat16*)(dh + off) = hi;
        *(__nv_bfloat16*)(dl + off) = lo;
    }
}

// ================= A-tile conversion (fp32 -> bf16 hi/lo, swizzled), optional BN ======
template <bool BN>
__device__ __forceinline__ void convert_A(char* sm, int base, const float* __restrict__ src,
                                          const float* __restrict__ scale,
                                          const float* __restrict__ shift,
                                          int n0, int tid)
{
    for (int idx = tid; idx < 4096; idx += 256) {
        int r  = idx >> 5;
        int kg = idx & 31;
        int n  = n0 + r;
        float4 v = make_float4(0.f, 0.f, 0.f, 0.f);
        if (n < NN) v = ((const float4*)src)[n * 32 + kg];
        if (BN) {
            float4 sc = ((const float4*)scale)[kg];
            float4 sh = ((const float4*)shift)[kg];
            v.x = fmaxf(fmaf(v.x, sc.x, sh.x), 0.f);
            v.y = fmaxf(fmaf(v.y, sc.y, sh.y), 0.f);
            v.z = fmaxf(fmaf(v.z, sc.z, sh.z), 0.f);
            v.w = fmaxf(fmaf(v.w, sc.w, sh.w), 0.f);
        }
        int off = swz(r, kg * 8);
        __nv_bfloat16 hx = __float2bfloat16(v.x);
        __nv_bfloat16 hy = __float2bfloat16(v.y);
        __nv_bfloat16 hz = __float2bfloat16(v.z);
        __nv_bfloat16 hw = __float2bfloat16(v.w);
        __nv_bfloat16 lx = __float2bfloat16(v.x - __bfloat162float(hx));
        __nv_bfloat16 ly = __float2bfloat16(v.y - __bfloat162float(hy));
        __nv_bfloat16 lz = __float2bfloat16(v.z - __bfloat162float(hz));
        __nv_bfloat16 lw = __float2bfloat16(v.w - __bfloat162float(hw));
        uint2 ph, pl;
        ph.x = ((uint32_t)__bfloat16_as_ushort(hy) << 16) | __bfloat16_as_ushort(hx);
        ph.y = ((uint32_t)__bfloat16_as_ushort(hw) << 16) | __bfloat16_as_ushort(hz);
        pl.x = ((uint32_t)__bfloat16_as_ushort(ly) << 16) | __bfloat16_as_ushort(lx);
        pl.y = ((uint32_t)__bfloat16_as_ushort(lw) << 16) | __bfloat16_as_ushort(lz);
        *(uint2*)(sm + base + off) = ph;
        *(uint2*)(sm + base + 32768 + off) = pl;
    }
}

// ================= MMA core =================
struct MmaCtx { int lrowA, lkgA, lnB, lkgB, wr, wc; };
__device__ __forceinline__ void mma_chunk(uint32_t smb, int abase, int bbase,
                                          const MmaCtx& c, float acc[2][8][4]) {
#pragma unroll
    for (int ks = 0; ks < 8; ks++) {
        uint32_t ah[2][4], al[2][4], bh[4][4], bl[4][4];
#pragma unroll
        for (int at = 0; at < 2; at++) {
            int row = c.wr * 32 + at * 16 + c.lrowA;
            int kb  = (ks * 2 + c.lkgA) * 16;
            uint32_t off = (uint32_t)swz(row, kb);
            ldsm4(ah[at], smb + abase + off);
            ldsm4(al[at], smb + abase + 32768 + off);
        }
#pragma unroll
        for (int bp = 0; bp < 4; bp++) {
            int nrow = c.wc * 64 + bp * 16 + c.lnB;
            int kb   = (ks * 2 + c.lkgB) * 16;
            uint32_t off = (uint32_t)swz(nrow, kb);
            ldsm4(bh[bp], smb + bbase + off);
            ldsm4(bl[bp], smb + bbase + 32768 + off);
        }
#pragma unroll
        for (int at = 0; at < 2; at++)
#pragma unroll
            for (int bp = 0; bp < 4; bp++)
#pragma unroll
                for (int hf = 0; hf < 2; hf++) {
                    float* d = acc[at][bp * 2 + hf];
                    mma16816(d, ah[at], &bh[bp][hf * 2]);
                    mma16816(d, ah[at], &bl[bp][hf * 2]);
                    mma16816(d, al[at], &bh[bp][hf * 2]);
                }
    }
}

// ================= batched layer-0 GEMM: all experts, A converted once =================
#define G0_B 131072
#define G0_TOTAL 196608

__global__ void __launch_bounds__(256, 1)
k_gemm0_all(const float* __restrict__ x, const float* __restrict__ agg0,
            const char* __restrict__ wth_all, const char* __restrict__ wtl_all,
            const float* __restrict__ bprm, float* __restrict__ h_all)
{
    extern __shared__ char sm[];
    uint32_t smb = smem_u32(sm);
    int tid = threadIdx.x, wid = tid >> 5, lane = tid & 31;
    int n0 = blockIdx.x * 128;
    MmaCtx c;
    c.wr = wid & 3; c.wc = wid >> 2;
    c.lrowA = lane & 15; c.lkgA = lane >> 4;
    c.lnB = (lane & 7) + ((lane >> 4) << 3); c.lkgB = (lane >> 3) & 1;
    int trow = lane >> 2, tc2 = lane & 3;

    convert_A<false>(sm, 0,     x,    nullptr, nullptr, n0, tid);
    convert_A<false>(sm, 65536, agg0, nullptr, nullptr, n0, tid);

    for (int e = 0; e < NEXP; e++) {
        float acc[2][8][4];
#pragma unroll
        for (int a = 0; a < 2; a++)
#pragma unroll
            for (int b = 0; b < 8; b++)
#pragma unroll
                for (int q = 0; q < 4; q++) acc[a][b][q] = 0.f;

        const char* wh = wth_all + (size_t)(e * 2) * 65536;
        const char* wl = wtl_all + (size_t)(e * 2) * 65536;

#pragma unroll
        for (int chunk = 0; chunk < 2; chunk++) {
            __syncthreads();
            {
                const uint4* s0 = (const uint4*)(wh + chunk * 32768);
                const uint4* s1 = (const uint4*)(wl + chunk * 32768);
                uint4* d0 = (uint4*)(sm + G0_B);
                uint4* d1 = (uint4*)(sm + G0_B + 32768);
                for (int i = tid; i < 2048; i += 256) { d0[i] = s0[i]; d1[i] = s1[i]; }
            }
            __syncthreads();
            mma_chunk(smb, chunk * 65536, G0_B, c, acc);
        }

        const float* be = bprm + (size_t)(e * 2) * DD;
        float2* o = (float2*)(h_all + (size_t)e * NN * DD);
#pragma unroll
        for (int bt = 0; bt < 8; bt++) {
            int col = c.wc * 64 + bt * 8 + tc2 * 2;
            float bx = be[col], by = be[col + 1];
            float sx = 0.f, sy = 0.f, qx = 0.f, qy = 0.f;
#pragma unroll
            for (int at = 0; at < 2; at++) {
                int r0 = n0 + c.wr * 32 + at * 16 + trow;
                float v0x = acc[at][bt][0] + bx, v0y = acc[at][bt][1] + by;
                float v1x = acc[at][bt][2] + bx, v1y = acc[at][bt][3] + by;
                if (r0 < NN) {
                    o[r0 * 64 + (col >> 1)] = make_float2(v0x, v0y);
                    sx += v0x; sy += v0y; qx += v0x * v0x; qy += v0y * v0y;
                }
                if (r0 + 8 < NN) {
                    o[(r0 + 8) * 64 + (col >> 1)] = make_float2(v1x, v1y);
                    sx += v1x; sy += v1y; qx += v1x * v1x; qy += v1y * v1y;
                }
            }
#pragma unroll
            for (int off = 4; off < 32; off <<= 1) {
                sx += __shfl_xor_sync(0xFFFFFFFF, sx, off);
                sy += __shfl_xor_sync(0xFFFFFFFF, sy, off);
                qx += __shfl_xor_sync(0xFFFFFFFF, qx, off);
                qy += __shfl_xor_sync(0xFFFFFFFF, qy, off);
            }
            if (lane < 4) {
                atomicAdd(&g_stats_s[e * DD + col], sx);
                atomicAdd(&g_stats_s[e * DD + col + 1], sy);
                atomicAdd(&g_stats_q[e * DD + col], qx);
                atomicAdd(&g_stats_q[e * DD + col + 1], qy);
            }
        }
    }
}

// ================= finalize BN =================
__global__ void k_finalize(const float* __restrict__ gamma, const float* __restrict__ beta) {
    int i = threadIdx.x + blockIdx.x * blockDim.x;
    if (i >= NEXP * DD) return;
    const float invn = 1.0f / (float)NN;
    float m = g_stats_s[i] * invn;
    float var = g_stats_q[i] * invn - m * m;
    float r = rsqrtf(var + EPSV);
    float sc = gamma[i] * r;
    g_scale[i] = sc;
    g_shift[i] = beta[i] - m * sc;
}

// ================= batched layer-1 GEMM: all experts in one launch ====================
#define G1_B 65536
#define G1_TOTAL 131072

__global__ void __launch_bounds__(256, 1)
k_gemm1_all(const float* __restrict__ h_all, const float* __restrict__ agg1_all,
            const char* __restrict__ wth_all, const char* __restrict__ wtl_all,
            const float* __restrict__ bprm,
            const float* __restrict__ scale, const float* __restrict__ shift,
            float* __restrict__ otmp)
{
    extern __shared__ char sm[];
    uint32_t smb = smem_u32(sm);
    int tid = threadIdx.x, wid = tid >> 5, lane = tid & 31;
    int n0 = blockIdx.x * 128;
    MmaCtx c;
    c.wr = wid & 3; c.wc = wid >> 2;
    c.lrowA = lane & 15; c.lkgA = lane >> 4;
    c.lnB = (lane & 7) + ((lane >> 4) << 3); c.lkgB = (lane >> 3) & 1;
    int trow = lane >> 2, tc2 = lane & 3;

    for (int e = 0; e < NEXP; e++) {
        float acc[2][8][4];
#pragma unroll
        for (int a = 0; a < 2; a++)
#pragma unroll
            for (int b = 0; b < 8; b++)
#pragma unroll
                for (int q = 0; q < 4; q++) acc[a][b][q] = 0.f;

        const char* wh = wth_all + (size_t)(e * 2 + 1) * 65536;
        const char* wl = wtl_all + (size_t)(e * 2 + 1) * 65536;
        const float* he = h_all    + (size_t)e * NN * DD;
        const float* ae = agg1_all + (size_t)e * NN * DD;

#pragma unroll
        for (int chunk = 0; chunk < 2; chunk++) {
            __syncthreads();
            {
                const uint4* s0 = (const uint4*)(wh + chunk * 32768);
                const uint4* s1 = (const uint4*)(wl + chunk * 32768);
                uint4* d0 = (uint4*)(sm + G1_B);
                uint4* d1 = (uint4*)(sm + G1_B + 32768);
                for (int i = tid; i < 2048; i += 256) { d0[i] = s0[i]; d1[i] = s1[i]; }
            }
            if (chunk == 0)
                convert_A<true>(sm, 0, he, scale + e * DD, shift + e * DD, n0, tid);
            else
                convert_A<false>(sm, 0, ae, nullptr, nullptr, n0, tid);
            __syncthreads();
            mma_chunk(smb, 0, G1_B, c, acc);
        }

        const float* be = bprm + (size_t)(e * 2 + 1) * DD;
        float2* o = (float2*)(otmp + (size_t)e * NN * DD);
#pragma unroll
        for (int at = 0; at < 2; at++)
#pragma unroll
            for (int bt = 0; bt < 8; bt++) {
                int col = c.wc * 64 + bt * 8 + tc2 * 2;
                float bx = be[col], by = be[col + 1];
                int r0 = n0 + c.wr * 32 + at * 16 + trow;
                if (r0 < NN)
                    o[r0 * 64 + (col >> 1)] =
                        make_float2(acc[at][bt][0] + bx, acc[at][bt][1] + by);
                if (r0 + 8 < NN)
                    o[(r0 + 8) * 64 + (col >> 1)] =
                        make_float2(acc[at][bt][2] + bx, acc[at][bt][3] + by);
            }
    }
}

// ================= final interleave [8][N][128] -> [N][128][8] =================
__global__ void k_interleave(float* __restrict__ out) {
    int idx = blockIdx.x * blockDim.x + threadIdx.x;
    if (idx >= NN * DD) return;
    float v[8];
#pragma unroll
    for (int e = 0; e < 8; e++) v[e] = g_out_tmp[(size_t)e * (NN * DD) + idx];
    float4* o = (float4*)out + (size_t)idx * 2;
    o[0] = make_float4(v[0], v[1], v[2], v[3]);
    o[1] = make_float4(v[4], v[5], v[6], v[7]);
}

// ================= launch =================
extern "C" void kernel_launch(void* const* d_in, const int* in_sizes, int n_in,
                              void* d_out, int out_size)
{
    const float* x      = (const float*)d_in[0];
    const int*   ei32   = (const int*)d_in[1];
    const float* W_self = (const float*)d_in[2];
    const float* W_nbr  = (const float*)d_in[3];
    const float* bprm   = (const float*)d_in[4];
    const float* gamma  = (const float*)d_in[5];
    const float* beta   = (const float*)d_in[6];
    float*       out    = (float*)d_out;

    cudaFuncSetAttribute(k_gemm0_all, cudaFuncAttributeMaxDynamicSharedMemorySize, G0_TOTAL);
    cudaFuncSetAttribute(k_gemm1_all, cudaFuncAttributeMaxDynamicSharedMemorySize, G1_TOTAL);

    float *agg0, *agg1, *hall, *otmp, *scl, *shf;
    char *wth, *wtl;
    cudaGetSymbolAddress((void**)&agg0, g_agg0);
    cudaGetSymbolAddress((void**)&agg1, g_agg1_all);
    cudaGetSymbolAddress((void**)&hall, g_h_all);
    cudaGetSymbolAddress((void**)&otmp, g_out_tmp);
    cudaGetSymbolAddress((void**)&scl,  g_scale);
    cudaGetSymbolAddress((void**)&shf,  g_shift);
    cudaGetSymbolAddress((void**)&wth,  g_wt_hi);
    cudaGetSymbolAddress((void**)&wtl,  g_wt_lo);

    const int NB = (NN + 127) / 128;   // 782

    // launch index:  0          1       2            3 (ncu-profiled)
    k_prep_w<<<16, 256>>>(W_self, W_nbr);
    k_init<<<1, 1024>>>(ei32);
    k_csr_agg0<<<NBLK, 256>>>(ei32, x, agg0);
    k_gemm0_all<<<NB, 256, G0_TOTAL>>>(x, agg0, wth, wtl, bprm, hall);
    k_finalize<<<1, 1024>>>(gamma, beta);

    for (int e = 0; e < NEXP; e++)
        k_agg<<<NN / 8, 256>>>(hall + (size_t)e * NN * DD,
                               agg1 + (size_t)e * NN * DD,
                               scl + e * DD, shf + e * DD);

    k_gemm1_all<<<NB, 256, G1_TOTAL>>>(hall, agg1, wth, wtl, bprm, scl, shf, otmp);
    k_interleave<<<(NN * DD) / 256, 256>>>(out);
}

// round 8
// speedup vs baseline: 1.3472x; 1.0635x over previous
#include <cuda_runtime.h>
#include <cuda_bf16.h>
#include <cstdint>

#define NN 100000
#define EE 1600000
#define DD 128
#define NEXP 8
#define EPSV 1e-5f
#define NBLK 296
#define GT (NBLK * 256)

// ================= scratch (static device globals) =================
__device__ int   g_deg[NN];
__device__ int   g_off[NN];
__device__ int   g_cur[NN];
__device__ float g_inv_deg[NN];
__device__ int   g_srcs[EE];
__device__ int   g_bsum2[NBLK];
__device__ int   g_barrier[8];
__device__ int   g_is64;
__device__ float g_agg0[NN * DD];
__device__ float g_stats_s[NEXP * DD];
__device__ float g_stats_q[NEXP * DD];
__device__ float g_scale[NEXP * DD];
__device__ float g_shift[NEXP * DD];
__device__ char  g_wt_hi[16][65536];     // per (e,l): 2 chunks x [128n][128k] bf16, swizzled
__device__ char  g_wt_lo[16][65536];
__device__ float g_h_all[(size_t)NEXP * NN * DD];     // [8][N][128] pre-BN layer-0 h
__device__ float g_agg1_all[(size_t)NEXP * NN * DD];  // [8][N][128]
__device__ float g_out_tmp[(size_t)NEXP * NN * DD];   // [8][N][128] layer-1 outputs

// ================= helpers =================
__device__ __forceinline__ uint32_t smem_u32(const void* p) {
    uint32_t a;
    asm("{ .reg .u64 t; cvta.to.shared.u64 t, %1; cvt.u32.u64 %0, t; }" : "=r"(a) : "l"(p));
    return a;
}
__device__ __forceinline__ void ldsm4(uint32_t* r, uint32_t addr) {
    asm volatile("ldmatrix.sync.aligned.m8n8.x4.shared.b16 {%0,%1,%2,%3}, [%4];"
        : "=r"(r[0]), "=r"(r[1]), "=r"(r[2]), "=r"(r[3]) : "r"(addr));
}
__device__ __forceinline__ void mma16816(float* d, const uint32_t* a, const uint32_t* b) {
    asm volatile("mma.sync.aligned.m16n8k16.row.col.f32.bf16.bf16.f32 "
        "{%0,%1,%2,%3}, {%4,%5,%6,%7}, {%8,%9}, {%0,%1,%2,%3};"
        : "+f"(d[0]), "+f"(d[1]), "+f"(d[2]), "+f"(d[3])
        : "r"(a[0]), "r"(a[1]), "r"(a[2]), "r"(a[3]), "r"(b[0]), "r"(b[1]));
}
__device__ __forceinline__ int swz(int row, int kbyte) {
    return row * 256 + ((((kbyte >> 4) ^ (row & 7)) << 4) | (kbyte & 15));
}
__device__ __forceinline__ void cp16(uint32_t dst, const void* src) {
    asm volatile("cp.async.cg.shared.global [%0], [%1], 16;" :: "r"(dst), "l"(src));
}
#define CP_COMMIT() asm volatile("cp.async.commit_group;" ::: "memory")
#define CP_WAIT1() asm volatile("cp.async.wait_group 1;" ::: "memory")
#define CP_WAIT0() asm volatile("cp.async.wait_group 0;" ::: "memory")

// ================= software grid barrier =================
__device__ __forceinline__ void grid_bar(int slot) {
    __syncthreads();
    if (threadIdx.x == 0) {
        __threadfence();
        int arrived = atomicAdd(&g_barrier[slot], 1) + 1;
        if (arrived < NBLK) {
            while (((volatile int*)g_barrier)[slot] < NBLK) { }
        }
        __threadfence();
    }
    __syncthreads();
}

// ================= init =================
__global__ void k_init(const int* __restrict__ ei32) {
    int t = threadIdx.x;
    if (t < 8) g_barrier[t] = 0;
    for (int i = t; i < NEXP * DD; i += 1024) { g_stats_s[i] = 0.f; g_stats_q[i] = 0.f; }
    if (t == 0) {
        int hz = 1;
        for (int i = 0; i < 64; i++)
            if (ei32[2 * i + 1] != 0) { hz = 0; break; }
        g_is64 = hz;
    }
}

// ================= fused CSR build + layer-0 aggregation =================
__global__ void __launch_bounds__(256)
k_csr_agg0(const int* __restrict__ ei32, const float* __restrict__ x,
           float* __restrict__ agg0)
{
    int tid = threadIdx.x, b = blockIdx.x;
    int gt = b * 256 + tid;
    __shared__ int s[256];
    __shared__ int bs[NBLK];

    for (int i = gt; i < NN; i += GT) g_deg[i] = 0;
    grid_bar(0);

    int is64 = g_is64;
    for (int i = gt; i < EE; i += GT) {
        int d = is64 ? ei32[2 * (EE + i)] : ei32[EE + i];
        if ((unsigned)d < NN) atomicAdd(&g_deg[d], 1);
    }
    grid_bar(1);

    int base0 = gt * 2;
    int d0 = (base0     < NN) ? g_deg[base0]     : 0;
    int d1 = (base0 + 1 < NN) ? g_deg[base0 + 1] : 0;
    int tsum = d0 + d1;
    s[tid] = tsum;
    __syncthreads();
    for (int o = 1; o < 256; o <<= 1) {
        int a = (tid >= o) ? s[tid - o] : 0;
        __syncthreads();
        s[tid] += a;
        __syncthreads();
    }
    if (tid == 255) g_bsum2[b] = s[255];
    grid_bar(2);

    if (b == 0) {
        for (int i = tid; i < NBLK; i += 256) bs[i] = g_bsum2[i];
        __syncthreads();
        if (tid == 0) {
            int run = 0;
            for (int i = 0; i < NBLK; i++) { int v = bs[i]; bs[i] = run; run += v; }
        }
        __syncthreads();
        for (int i = tid; i < NBLK; i += 256) g_bsum2[i] = bs[i];
    }
    grid_bar(3);

    {
        int tbase = g_bsum2[b] + (s[tid] - tsum);
        if (base0 < NN) {
            g_off[base0] = tbase;
            g_cur[base0] = tbase;
            g_inv_deg[base0] = 1.0f / (float)(d0 > 0 ? d0 : 1);
        }
        if (base0 + 1 < NN) {
            int o1 = tbase + d0;
            g_off[base0 + 1] = o1;
            g_cur[base0 + 1] = o1;
            g_inv_deg[base0 + 1] = 1.0f / (float)(d1 > 0 ? d1 : 1);
        }
    }
    grid_bar(4);

    for (int i = gt; i < EE; i += GT) {
        int d  = is64 ? ei32[2 * (EE + i)] : ei32[EE + i];
        int sv = is64 ? ei32[2 * i]        : ei32[i];
        if ((unsigned)d < NN && (unsigned)sv < NN) {
            int pos = atomicAdd(&g_cur[d], 1);
            g_srcs[pos] = sv;
        }
    }
    grid_bar(5);

    {
        int gw = gt >> 5, lane = tid & 31;
        const int NW = NBLK * 8;
        const float4* f4 = (const float4*)x;
        for (int node = gw; node < NN; node += NW) {
            int start = g_off[node];
            int cnt   = g_cur[node] - start;
            float4 acc = make_float4(0.f, 0.f, 0.f, 0.f);
            int j = 0;
#define GB(U) \
            { \
                int si[U]; \
                _Pragma("unroll") for (int u = 0; u < U; u++) si[u] = g_srcs[start + j + u]; \
                float4 v[U]; \
                _Pragma("unroll") for (int u = 0; u < U; u++) v[u] = f4[si[u] * 32 + lane]; \
                _Pragma("unroll") for (int u = 0; u < U; u++) { \
                    acc.x += v[u].x; acc.y += v[u].y; acc.z += v[u].z; acc.w += v[u].w; \
                } \
                j += U; \
            }
            for (; j + 8 <= cnt;) GB(8)
            if (j + 4 <= cnt) GB(4)
            if (j + 2 <= cnt) GB(2)
            if (j + 1 <= cnt) GB(1)
#undef GB
            float scv = g_inv_deg[node];
            ((float4*)agg0)[node * 32 + lane] =
                make_float4(acc.x * scv, acc.y * scv, acc.z * scv, acc.w * scv);
        }
    }
}

// ================= per-expert layer-1 aggregation (BN+ReLU on gather) =================
__global__ void k_agg(const float* __restrict__ feat, float* __restrict__ out,
                      const float* __restrict__ scale, const float* __restrict__ shift)
{
    int gw = (blockIdx.x * blockDim.x + threadIdx.x) >> 5;
    int lane = threadIdx.x & 31;
    if (gw >= NN) return;
    int start = g_off[gw];
    int cnt   = g_cur[gw] - start;
    const float4* f4 = (const float4*)feat;
    float4 sc4 = ((const float4*)scale)[lane];
    float4 sh4 = ((const float4*)shift)[lane];
    float4 acc = make_float4(0.f, 0.f, 0.f, 0.f);
    int j = 0;
#define GB(U) \
    { \
        int si[U]; \
        _Pragma("unroll") for (int u = 0; u < U; u++) si[u] = g_srcs[start + j + u]; \
        float4 v[U]; \
        _Pragma("unroll") for (int u = 0; u < U; u++) v[u] = f4[si[u] * 32 + lane]; \
        _Pragma("unroll") for (int u = 0; u < U; u++) { \
            float4 t = v[u]; \
            t.x = fmaxf(fmaf(t.x, sc4.x, sh4.x), 0.f); \
            t.y = fmaxf(fmaf(t.y, sc4.y, sh4.y), 0.f); \
            t.z = fmaxf(fmaf(t.z, sc4.z, sh4.z), 0.f); \
            t.w = fmaxf(fmaf(t.w, sc4.w, sh4.w), 0.f); \
            acc.x += t.x; acc.y += t.y; acc.z += t.z; acc.w += t.w; \
        } \
        j += U; \
    }
    for (; j + 8 <= cnt;) GB(8)
    if (j + 4 <= cnt) GB(4)
    if (j + 2 <= cnt) GB(2)
    if (j + 1 <= cnt) GB(1)
#undef GB
    float scv = g_inv_deg[gw];
    ((float4*)out)[gw * 32 + lane] =
        make_float4(acc.x * scv, acc.y * scv, acc.z * scv, acc.w * scv);
}

// ================= weight prep =================
__global__ void k_prep_w(const float* __restrict__ Wself, const float* __restrict__ Wnbr) {
    int inst = blockIdx.x;
    const float* ws = Wself + (size_t)inst * DD * DD;
    const float* wn = Wnbr  + (size_t)inst * DD * DD;
    char* dh = g_wt_hi[inst];
    char* dl = g_wt_lo[inst];
    for (int idx = threadIdx.x; idx < 256 * 128; idx += blockDim.x) {
        int n = idx & 127;
        int k = idx >> 7;
        float w = (k < 128) ? ws[k * 128 + n] : wn[(k - 128) * 128 + n];
        __nv_bfloat16 hi = __float2bfloat16(w);
        __nv_bfloat16 lo = __float2bfloat16(w - __bfloat162float(hi));
        int chunk = k >> 7;
        int kk = k & 127;
        int off = chunk * 32768 + swz(n, kk * 2);
        *(__nv_bfloat16*)(dh + off) = hi;
        *(__nv_bfloat16*)(dl + off) = lo;
    }
}

// ================= A-tile conversion =================
template <bool BN>
__device__ __forceinline__ void convert_A(char* sm, int base, const float* __restrict__ src,
                                          const float* __restrict__ scale,
                                          const float* __restrict__ shift,
                                          int n0, int tid)
{
    for (int idx = tid; idx < 4096; idx += 256) {
        int r  = idx >> 5;
        int kg = idx & 31;
        int n  = n0 + r;
        float4 v = make_float4(0.f, 0.f, 0.f, 0.f);
        if (n < NN) v = ((const float4*)src)[n * 32 + kg];
        if (BN) {
            float4 sc = ((const float4*)scale)[kg];
            float4 sh = ((const float4*)shift)[kg];
            v.x = fmaxf(fmaf(v.x, sc.x, sh.x), 0.f);
            v.y = fmaxf(fmaf(v.y, sc.y, sh.y), 0.f);
            v.z = fmaxf(fmaf(v.z, sc.z, sh.z), 0.f);
            v.w = fmaxf(fmaf(v.w, sc.w, sh.w), 0.f);
        }
        int off = swz(r, kg * 8);
        __nv_bfloat16 hx = __float2bfloat16(v.x);
        __nv_bfloat16 hy = __float2bfloat16(v.y);
        __nv_bfloat16 hz = __float2bfloat16(v.z);
        __nv_bfloat16 hw = __float2bfloat16(v.w);
        __nv_bfloat16 lx = __float2bfloat16(v.x - __bfloat162float(hx));
        __nv_bfloat16 ly = __float2bfloat16(v.y - __bfloat162float(hy));
        __nv_bfloat16 lz = __float2bfloat16(v.z - __bfloat162float(hz));
        __nv_bfloat16 lw = __float2bfloat16(v.w - __bfloat162float(hw));
        uint2 ph, pl;
        ph.x = ((uint32_t)__bfloat16_as_ushort(hy) << 16) | __bfloat16_as_ushort(hx);
        ph.y = ((uint32_t)__bfloat16_as_ushort(hw) << 16) | __bfloat16_as_ushort(hz);
        pl.x = ((uint32_t)__bfloat16_as_ushort(ly) << 16) | __bfloat16_as_ushort(lx);
        pl.y = ((uint32_t)__bfloat16_as_ushort(lw) << 16) | __bfloat16_as_ushort(lz);
        *(uint2*)(sm + base + off) = ph;
        *(uint2*)(sm + base + 32768 + off) = pl;
    }
}

// ================= MMA tile pass: acc += A_hi@B (+ A_lo@B if dual) =================
struct MmaCtx { int lrowA, lkgA, lnB, lkgB, wr, wc; };

template <bool DUAL>
__device__ __forceinline__ void mma_pass(uint32_t smb, int ahbase, int albase, int bbase,
                                         const MmaCtx& c, float acc[2][8][4]) {
#pragma unroll
    for (int ks = 0; ks < 8; ks++) {
        uint32_t ah[2][4], al[2][4], bb[4][4];
#pragma unroll
        for (int at = 0; at < 2; at++) {
            int row = c.wr * 32 + at * 16 + c.lrowA;
            int kb  = (ks * 2 + c.lkgA) * 16;
            uint32_t off = (uint32_t)swz(row, kb);
            ldsm4(ah[at], smb + ahbase + off);
            if (DUAL) ldsm4(al[at], smb + albase + off);
        }
#pragma unroll
        for (int bp = 0; bp < 4; bp++) {
            int nrow = c.wc * 64 + bp * 16 + c.lnB;
            int kb   = (ks * 2 + c.lkgB) * 16;
            ldsm4(bb[bp], smb + bbase + (uint32_t)swz(nrow, kb));
        }
#pragma unroll
        for (int at = 0; at < 2; at++)
#pragma unroll
            for (int bp = 0; bp < 4; bp++)
#pragma unroll
                for (int hf = 0; hf < 2; hf++) {
                    float* d = acc[at][bp * 2 + hf];
                    mma16816(d, ah[at], &bb[bp][hf * 2]);
                    if (DUAL) mma16816(d, al[at], &bb[bp][hf * 2]);
                }
    }
}

// tile t (0..31): e=t>>2, sub=t&3, chunk=sub>>1, which=sub&1 (0=hi,1=lo)
__device__ __forceinline__ void issue_b(uint32_t smb, uint32_t bufbase,
                                        const char* wth_all, const char* wtl_all,
                                        int layer, int t, int tid) {
    int e = t >> 2, sub = t & 3, chunk = sub >> 1, which = sub & 1;
    const char* src = (which ? wtl_all : wth_all)
                    + (size_t)(e * 2 + layer) * 65536 + chunk * 32768;
    uint32_t dst = smb + bufbase + (uint32_t)(t & 1) * 32768;
#pragma unroll
    for (int i = 0; i < 8; i++) {
        int idx = tid + i * 256;
        cp16(dst + idx * 16, src + idx * 16);
    }
    CP_COMMIT();
}

// ================= batched layer-0 GEMM (pipelined B) =================
// smem: A [c0hi,c0lo,c1hi,c1lo] 0..131071 ; B double-buffer 131072..196607
#define G0_B 131072
#define G0_TOTAL 196608

__global__ void __launch_bounds__(256, 1)
k_gemm0_all(const float* __restrict__ x, const float* __restrict__ agg0,
            const char* __restrict__ wth_all, const char* __restrict__ wtl_all,
            const float* __restrict__ bprm, float* __restrict__ h_all)
{
    extern __shared__ char sm[];
    uint32_t smb = smem_u32(sm);
    int tid = threadIdx.x, wid = tid >> 5, lane = tid & 31;
    int n0 = blockIdx.x * 128;
    MmaCtx c;
    c.wr = wid & 3; c.wc = wid >> 2;
    c.lrowA = lane & 15; c.lkgA = lane >> 4;
    c.lnB = (lane & 7) + ((lane >> 4) << 3); c.lkgB = (lane >> 3) & 1;
    int trow = lane >> 2, tc2 = lane & 3;

    convert_A<false>(sm, 0,     x,    nullptr, nullptr, n0, tid);
    convert_A<false>(sm, 65536, agg0, nullptr, nullptr, n0, tid);

    issue_b(smb, G0_B, wth_all, wtl_all, 0, 0, tid);

    float acc[2][8][4];
#pragma unroll
    for (int a = 0; a < 2; a++)
#pragma unroll
        for (int b = 0; b < 8; b++)
#pragma unroll
            for (int q = 0; q < 4; q++) acc[a][b][q] = 0.f;

    for (int e = 0; e < NEXP; e++) {
#pragma unroll
        for (int sub = 0; sub < 4; sub++) {
            int t = e * 4 + sub;
            if (t + 1 < 32) {
                issue_b(smb, G0_B, wth_all, wtl_all, 0, t + 1, tid);
                CP_WAIT1();
            } else {
                CP_WAIT0();
            }
            __syncthreads();
            int ab = (sub >> 1) * 65536;
            int bbase = G0_B + (t & 1) * 32768;
            if ((sub & 1) == 0)
                mma_pass<true>(smb, ab, ab + 32768, bbase, c, acc);
            else
                mma_pass<false>(smb, ab, 0, bbase, c, acc);

            if (sub == 3) {
                // epilogue: bias, store h, fused column stats; reset acc
                const float* be = bprm + (size_t)(e * 2) * DD;
                float2* o = (float2*)(h_all + (size_t)e * NN * DD);
#pragma unroll
                for (int bt = 0; bt < 8; bt++) {
                    int col = c.wc * 64 + bt * 8 + tc2 * 2;
                    float bx = be[col], by = be[col + 1];
                    float sx = 0.f, sy = 0.f, qx = 0.f, qy = 0.f;
#pragma unroll
                    for (int at = 0; at < 2; at++) {
                        int r0 = n0 + c.wr * 32 + at * 16 + trow;
                        float v0x = acc[at][bt][0] + bx, v0y = acc[at][bt][1] + by;
                        float v1x = acc[at][bt][2] + bx, v1y = acc[at][bt][3] + by;
                        if (r0 < NN) {
                            o[r0 * 64 + (col >> 1)] = make_float2(v0x, v0y);
                            sx += v0x; sy += v0y; qx += v0x * v0x; qy += v0y * v0y;
                        }
                        if (r0 + 8 < NN) {
                            o[(r0 + 8) * 64 + (col >> 1)] = make_float2(v1x, v1y);
                            sx += v1x; sy += v1y; qx += v1x * v1x; qy += v1y * v1y;
                        }
                    }
#pragma unroll
                    for (int off = 4; off < 32; off <<= 1) {
                        sx += __shfl_xor_sync(0xFFFFFFFF, sx, off);
                        sy += __shfl_xor_sync(0xFFFFFFFF, sy, off);
                        qx += __shfl_xor_sync(0xFFFFFFFF, qx, off);
                        qy += __shfl_xor_sync(0xFFFFFFFF, qy, off);
                    }
                    if (lane < 4) {
                        atomicAdd(&g_stats_s[e * DD + col], sx);
                        atomicAdd(&g_stats_s[e * DD + col + 1], sy);
                        atomicAdd(&g_stats_q[e * DD + col], qx);
                        atomicAdd(&g_stats_q[e * DD + col + 1], qy);
                    }
                }
#pragma unroll
                for (int a = 0; a < 2; a++)
#pragma unroll
                    for (int b = 0; b < 8; b++)
#pragma unroll
                        for (int q = 0; q < 4; q++) acc[a][b][q] = 0.f;
            }
            __syncthreads();
        }
    }
}

// ================= finalize BN =================
__global__ void k_finalize(const float* __restrict__ gamma, const float* __restrict__ beta) {
    int i = threadIdx.x + blockIdx.x * blockDim.x;
    if (i >= NEXP * DD) return;
    const float invn = 1.0f / (float)NN;
    float m = g_stats_s[i] * invn;
    float var = g_stats_q[i] * invn - m * m;
    float r = rsqrtf(var + EPSV);
    float sc = gamma[i] * r;
    g_scale[i] = sc;
    g_shift[i] = beta[i] - m * sc;
}

// ================= batched layer-1 GEMM (pipelined B, per-chunk A convert) ============
// smem: A [hi,lo] 0..65535 ; B double-buffer 65536..131071
#define G1_B 65536
#define G1_TOTAL 131072

__global__ void __launch_bounds__(256, 1)
k_gemm1_all(const float* __restrict__ h_all, const float* __restrict__ agg1_all,
            const char* __restrict__ wth_all, const char* __restrict__ wtl_all,
            const float* __restrict__ bprm,
            const float* __restrict__ scale, const float* __restrict__ shift,
            float* __restrict__ otmp)
{
    extern __shared__ char sm[];
    uint32_t smb = smem_u32(sm);
    int tid = threadIdx.x, wid = tid >> 5, lane = tid & 31;
    int n0 = blockIdx.x * 128;
    MmaCtx c;
    c.wr = wid & 3; c.wc = wid >> 2;
    c.lrowA = lane & 15; c.lkgA = lane >> 4;
    c.lnB = (lane & 7) + ((lane >> 4) << 3); c.lkgB = (lane >> 3) & 1;
    int trow = lane >> 2, tc2 = lane & 3;

    issue_b(smb, G1_B, wth_all, wtl_all, 1, 0, tid);

    float acc[2][8][4];
#pragma unroll
    for (int a = 0; a < 2; a++)
#pragma unroll
        for (int b = 0; b < 8; b++)
#pragma unroll
            for (int q = 0; q < 4; q++) acc[a][b][q] = 0.f;

    for (int e = 0; e < NEXP; e++) {
        const float* he = h_all    + (size_t)e * NN * DD;
        const float* ae = agg1_all + (size_t)e * NN * DD;
#pragma unroll
        for (int sub = 0; sub < 4; sub++) {
            int t = e * 4 + sub;
            if (t + 1 < 32) issue_b(smb, G1_B, wth_all, wtl_all, 1, t + 1, tid);
            // A conversion overlaps with in-flight B prefetch
            if (sub == 0)
                convert_A<true>(sm, 0, he, scale + e * DD, shift + e * DD, n0, tid);
            else if (sub == 2)
                convert_A<false>(sm, 0, ae, nullptr, nullptr, n0, tid);
            if (t + 1 < 32) { CP_WAIT1(); } else { CP_WAIT0(); }
            __syncthreads();
            int bbase = G1_B + (t & 1) * 32768;
            if ((sub & 1) == 0)
                mma_pass<true>(smb, 0, 32768, bbase, c, acc);
            else
                mma_pass<false>(smb, 0, 0, bbase, c, acc);

            if (sub == 3) {
                const float* be = bprm + (size_t)(e * 2 + 1) * DD;
                float2* o = (float2*)(otmp + (size_t)e * NN * DD);
#pragma unroll
                for (int at = 0; at < 2; at++)
#pragma unroll
                    for (int bt = 0; bt < 8; bt++) {
                        int col = c.wc * 64 + bt * 8 + tc2 * 2;
                        float bx = be[col], by = be[col + 1];
                        int r0 = n0 + c.wr * 32 + at * 16 + trow;
                        if (r0 < NN)
                            o[r0 * 64 + (col >> 1)] =
                                make_float2(acc[at][bt][0] + bx, acc[at][bt][1] + by);
                        if (r0 + 8 < NN)
                            o[(r0 + 8) * 64 + (col >> 1)] =
                                make_float2(acc[at][bt][2] + bx, acc[at][bt][3] + by);
                    }
#pragma unroll
                for (int a = 0; a < 2; a++)
#pragma unroll
                    for (int b = 0; b < 8; b++)
#pragma unroll
                        for (int q = 0; q < 4; q++) acc[a][b][q] = 0.f;
            }
            __syncthreads();
        }
    }
}

// ================= final interleave [8][N][128] -> [N][128][8] =================
__global__ void k_interleave(float* __restrict__ out) {
    int idx = blockIdx.x * blockDim.x + threadIdx.x;
    if (idx >= NN * DD) return;
    float v[8];
#pragma unroll
    for (int e = 0; e < 8; e++) v[e] = g_out_tmp[(size_t)e * (NN * DD) + idx];
    float4* o = (float4*)out + (size_t)idx * 2;
    o[0] = make_float4(v[0], v[1], v[2], v[3]);
    o[1] = make_float4(v[4], v[5], v[6], v[7]);
}

// ================= launch =================
extern "C" void kernel_launch(void* const* d_in, const int* in_sizes, int n_in,
                              void* d_out, int out_size)
{
    const float* x      = (const float*)d_in[0];
    const int*   ei32   = (const int*)d_in[1];
    const float* W_self = (const float*)d_in[2];
    const float* W_nbr  = (const float*)d_in[3];
    const float* bprm   = (const float*)d_in[4];
    const float* gamma  = (const float*)d_in[5];
    const float* beta   = (const float*)d_in[6];
    float*       out    = (float*)d_out;

    cudaFuncSetAttribute(k_gemm0_all, cudaFuncAttributeMaxDynamicSharedMemorySize, G0_TOTAL);
    cudaFuncSetAttribute(k_gemm1_all, cudaFuncAttributeMaxDynamicSharedMemorySize, G1_TOTAL);

    float *agg0, *agg1, *hall, *otmp, *scl, *shf;
    char *wth, *wtl;
    cudaGetSymbolAddress((void**)&agg0, g_agg0);
    cudaGetSymbolAddress((void**)&agg1, g_agg1_all);
    cudaGetSymbolAddress((void**)&hall, g_h_all);
    cudaGetSymbolAddress((void**)&otmp, g_out_tmp);
    cudaGetSymbolAddress((void**)&scl,  g_scale);
    cudaGetSymbolAddress((void**)&shf,  g_shift);
    cudaGetSymbolAddress((void**)&wth,  g_wt_hi);
    cudaGetSymbolAddress((void**)&wtl,  g_wt_lo);

    const int NB = (NN + 127) / 128;   // 782

    // launch index:  0          1       2            3 (ncu-profiled)
    k_prep_w<<<16, 256>>>(W_self, W_nbr);
    k_init<<<1, 1024>>>(ei32);
    k_csr_agg0<<<NBLK, 256>>>(ei32, x, agg0);
    k_gemm0_all<<<NB, 256, G0_TOTAL>>>(x, agg0, wth, wtl, bprm, hall);
    k_finalize<<<1, 1024>>>(gamma, beta);

    for (int e = 0; e < NEXP; e++)
        k_agg<<<NN / 8, 256>>>(hall + (size_t)e * NN * DD,
                               agg1 + (size_t)e * NN * DD,
                               scl + e * DD, shf + e * DD);

    k_gemm1_all<<<NB, 256, G1_TOTAL>>>(hall, agg1, wth, wtl, bprm, scl, shf, otmp);
    k_interleave<<<(NN * DD) / 256, 256>>>(out);
}